// round 6
// baseline (speedup 1.0000x reference)
#include <cuda_runtime.h>
#include <cstdint>

// Problem constants (fixed by the reference generator)
#define NPTS        2000000
#define NUM_PTS3D   500000
#define NUM_GROUPS  10000
#define NUM_POS     8
#define NUM_CAMS    8

#define PAD_CHUNKS  (NUM_PTS3D / 4)            // 125000 (4 points per thread)
#define PAD_BLOCKS  ((PAD_CHUNKS + 255) / 256) // 489
#define COMP_N      (NUM_GROUPS * NUM_POS)     // 80000
#define COMP_BLOCKS ((COMP_N + 255) / 256)     // 313

// Scratch: composed pose table (80000 x {t(float4), q(float4)}) = 2.56 MB,
// padded 3D points (500000 x float4) = 8 MB, merged camera table (8 x float4).
// All L2-resident.
__device__ float4 g_comp[COMP_N * 2];
__device__ float4 g_pts[NUM_PTS3D];
__device__ float4 g_cam[NUM_CAMS];

__device__ __forceinline__ float3 f3cross(float3 a, float3 b) {
    return make_float3(a.y * b.z - a.z * b.y,
                       a.z * b.x - a.x * b.z,
                       a.x * b.y - a.y * b.x);
}

// Fused prep kernel:
//  blocks [0, PAD_BLOCKS)                       : pad points_3d [N,3] -> float4 (4 pts/thread)
//  blocks [PAD_BLOCKS, PAD_BLOCKS+COMP_BLOCKS)  : compose ref x rel SE3 poses
//  block  PAD_BLOCKS+COMP_BLOCKS                : build merged camera table
__global__ __launch_bounds__(256) void prep_kernel(const float* __restrict__ p3d,
                                                   const float* __restrict__ ref_poses,
                                                   const float* __restrict__ rel_poses,
                                                   const float2* __restrict__ intrs,
                                                   const float2* __restrict__ pps) {
    int b = blockIdx.x;
    if (b < PAD_BLOCKS) {
        int c = b * 256 + threadIdx.x;           // chunk of 4 points
        if (c >= PAD_CHUNKS) return;
        const float4* in = (const float4*)p3d;   // 375000 float4s
        float4 a = __ldcs(in + 3 * c);
        float4 d = __ldcs(in + 3 * c + 1);
        float4 e = __ldcs(in + 3 * c + 2);
        int o = 4 * c;
        g_pts[o]     = make_float4(a.x, a.y, a.z, 0.0f);
        g_pts[o + 1] = make_float4(a.w, d.x, d.y, 0.0f);
        g_pts[o + 2] = make_float4(d.z, d.w, e.x, 0.0f);
        g_pts[o + 3] = make_float4(e.y, e.z, e.w, 0.0f);
        return;
    }
    if (b == PAD_BLOCKS + COMP_BLOCKS) {
        int t = threadIdx.x;
        if (t < NUM_CAMS) {
            float2 K  = intrs[t];
            float2 pp = pps[t];
            g_cam[t] = make_float4(K.x, K.y, pp.x, pp.y);
        }
        return;
    }

    int i = (b - PAD_BLOCKS) * 256 + threadIdx.x;
    if (i >= COMP_N) return;
    int g = i >> 3;          // group
    int m = i & 7;           // member
    const float* R = ref_poses + g * 7;
    const float* L = rel_poses + m * 7;

    float3 rt = make_float3(R[0], R[1], R[2]);
    float4 rq = make_float4(R[3], R[4], R[5], R[6]);
    float3 lt = make_float3(L[0], L[1], L[2]);
    float4 lq = make_float4(L[3], L[4], L[5], L[6]);

    // t = rel.t + rot(rel.q, ref.t)
    float3 v  = make_float3(lq.x, lq.y, lq.z);
    float3 uv = f3cross(v, rt);
    float3 uuv = f3cross(v, uv);
    float3 t = make_float3(lt.x + rt.x + 2.0f * (lq.w * uv.x + uuv.x),
                           lt.y + rt.y + 2.0f * (lq.w * uv.y + uuv.y),
                           lt.z + rt.z + 2.0f * (lq.w * uv.z + uuv.z));

    // q = lq * rq (Hamilton, [x,y,z,w])
    float3 v2 = make_float3(rq.x, rq.y, rq.z);
    float w  = lq.w * rq.w - (v.x * v2.x + v.y * v2.y + v.z * v2.z);
    float3 cx = f3cross(v, v2);
    float3 qv = make_float3(lq.w * v2.x + rq.w * v.x + cx.x,
                            lq.w * v2.y + rq.w * v.y + cx.y,
                            lq.w * v2.z + rq.w * v.z + cx.z);

    g_comp[2 * i]     = make_float4(t.x, t.y, t.z, 0.0f);
    g_comp[2 * i + 1] = make_float4(qv.x, qv.y, qv.z, w);
}

// Main reprojection: each thread handles 2 consecutive observations.
// Streaming loads use .cs (evict-first) so the gather tables keep L2 residency.
__global__ __launch_bounds__(256) void project_kernel(
    const float4* __restrict__ points_2d,       // pairs of obs
    const int2*   __restrict__ camera_indices,  // pairs
    const int4*   __restrict__ grouping_indices,// pairs of (g,m)
    const int2*   __restrict__ point_indices,   // pairs
    float4*       __restrict__ out)             // pairs of residuals
{
    __shared__ float4 s_cam[NUM_CAMS];
    if (threadIdx.x < NUM_CAMS) s_cam[threadIdx.x] = g_cam[threadIdx.x];
    __syncthreads();

    int t = blockIdx.x * blockDim.x + threadIdx.x;
    if (t >= NPTS / 2) return;

    // All independent streaming loads up front (MLP), evict-first
    int4   gm   = __ldcs(grouping_indices + t);
    int2   pi   = __ldcs(point_indices + t);
    int2   ci   = __ldcs(camera_indices + t);
    float4 obs  = __ldcs(points_2d + t);

    int base0 = (gm.x * NUM_POS + gm.y) * 2;
    int base1 = (gm.z * NUM_POS + gm.w) * 2;
    float4 tc0 = __ldg(g_comp + base0);
    float4 q0  = __ldg(g_comp + base0 + 1);
    float4 tc1 = __ldg(g_comp + base1);
    float4 q1  = __ldg(g_comp + base1 + 1);
    float4 p0  = __ldg(g_pts + pi.x);
    float4 p1  = __ldg(g_pts + pi.y);

    float4 cam0 = s_cam[ci.x];
    float4 cam1 = s_cam[ci.y];

    float4 r;
    {
        float3 v  = make_float3(q0.x, q0.y, q0.z);
        float3 p3 = make_float3(p0.x, p0.y, p0.z);
        float3 uv = f3cross(v, p3);
        float3 uuv = f3cross(v, uv);
        float px = p3.x + 2.0f * (q0.w * uv.x + uuv.x) + tc0.x;
        float py = p3.y + 2.0f * (q0.w * uv.y + uuv.y) + tc0.y;
        float pz = p3.z + 2.0f * (q0.w * uv.z + uuv.z) + tc0.z;
        float iz = __fdividef(1.0f, pz);
        r.x = fmaf(cam0.x, px * iz, cam0.z) - obs.x;
        r.y = fmaf(cam0.y, py * iz, cam0.w) - obs.y;
    }
    {
        float3 v  = make_float3(q1.x, q1.y, q1.z);
        float3 p3 = make_float3(p1.x, p1.y, p1.z);
        float3 uv = f3cross(v, p3);
        float3 uuv = f3cross(v, uv);
        float px = p3.x + 2.0f * (q1.w * uv.x + uuv.x) + tc1.x;
        float py = p3.y + 2.0f * (q1.w * uv.y + uuv.y) + tc1.y;
        float pz = p3.z + 2.0f * (q1.w * uv.z + uuv.z) + tc1.z;
        float iz = __fdividef(1.0f, pz);
        r.z = fmaf(cam1.x, px * iz, cam1.z) - obs.z;
        r.w = fmaf(cam1.y, py * iz, cam1.w) - obs.w;
    }
    __stcs(out + t, r);
}

extern "C" void kernel_launch(void* const* d_in, const int* in_sizes, int n_in,
                              void* d_out, int out_size) {
    const float* points_2d   = (const float*)d_in[0];
    const int*   cam_idx     = (const int*)d_in[1];
    const int*   grp_idx     = (const int*)d_in[2];
    const int*   pt_idx      = (const int*)d_in[3];
    const float* camera_pps  = (const float*)d_in[4];
    const float* intrs       = (const float*)d_in[5];
    const float* points_3d   = (const float*)d_in[6];
    const float* ref_poses   = (const float*)d_in[7];
    const float* rel_poses   = (const float*)d_in[8];

    prep_kernel<<<PAD_BLOCKS + COMP_BLOCKS + 1, 256>>>(
        points_3d, ref_poses, rel_poses,
        (const float2*)intrs, (const float2*)camera_pps);
    project_kernel<<<(NPTS / 2 + 255) / 256, 256>>>(
        (const float4*)points_2d, (const int2*)cam_idx, (const int4*)grp_idx,
        (const int2*)pt_idx, (float4*)d_out);
}